// round 15
// baseline (speedup 1.0000x reference)
#include <cuda_runtime.h>
#include <math_constants.h>

// Banded sparse attention, B=256, S=128, D=1024, H=16, Dh=64, |i-j|<=4.
// No smem. 8-lane group handles 4 consecutive queries (12-row shared band).
// SINGLE fused pass (flash-style): per band row, load k-row AND v-row
// (4 independent LDG.128 -> 2x MLP), packed-butterfly reduce 4 scores
// (4 shfl), exp-on-the-fly, broadcast unnormalized weight, accumulate
// acc += e*v. Normalize by owner-lane sum at the end. No w[] array,
// no second pass.

#define SEQ    128
#define DMODEL 1024
#define NHEADS 16
#define HEADD  64
#define HW     4
#define QPG    4              // queries per group
#define NT     (QPG + 2*HW)   // 12 band rows per group
#define QT     64             // queries per CTA
#define SCALE  0.125f
#define FULLM  0xffffffffu

__device__ __forceinline__ float dot4(const float4 a, const float4 b) {
    return a.x * b.x + a.y * b.y + a.z * b.z + a.w * b.w;
}
__device__ __forceinline__ void fma4(float4& a, float w, const float4 v) {
    a.x += w * v.x; a.y += w * v.y; a.z += w * v.z; a.w += w * v.w;
}

__global__ __launch_bounds__(128, 5)
void banded_attn_kernel(const float* __restrict__ q,
                        const float* __restrict__ k,
                        const float* __restrict__ v,
                        float* __restrict__ out)
{
    const int b   = blockIdx.z;
    const int h   = blockIdx.y;
    const int q0  = blockIdx.x * QT;
    const int tid = threadIdx.x;

    const int g   = tid >> 3;          // group 0..15
    const int s   = tid & 7;           // lane in group; owns float4 cols 2s,2s+1
    const int i0  = q0 + g * QPG;      // first query of group
    const int j0g = i0 - HW;
    const int mos = ((s & 1) << 1) | ((s >> 1) & 1);   // owned query index

    const size_t base = ((size_t)b * SEQ) * DMODEL + (size_t)h * HEADD;

    // ---- q rows (8 dims per lane per query) ----
    float4 qv[QPG][2];
#pragma unroll
    for (int m = 0; m < QPG; ++m) {
        const float4* qp = (const float4*)(q + base + (size_t)(i0 + m) * DMODEL);
        qv[m][0] = qp[2 * s];
        qv[m][1] = qp[2 * s + 1];
    }

    // ---- Fused band loop ----
    float4 acc[QPG][2];
#pragma unroll
    for (int m = 0; m < QPG; ++m) {
        acc[m][0] = make_float4(0.f, 0.f, 0.f, 0.f);
        acc[m][1] = acc[m][0];
    }
    float sum = 0.f;                   // owner-lane sum for query mos

    const float* kb = k + base;
    const float* vb = v + base;

#pragma unroll
    for (int t = 0; t < NT; ++t) {
        const int j = j0g + t;
        const bool valid = (j >= 0) && (j < SEQ);

        // k-row + v-row loads issued together: 4 independent LDG.128
        float4 k0 = make_float4(0.f, 0.f, 0.f, 0.f), k1 = k0;
        float4 v0 = k0, v1 = k0;
        if (valid) {
            const float4* kr = (const float4*)(kb + (size_t)j * DMODEL);
            const float4* vr = (const float4*)(vb + (size_t)j * DMODEL);
            k0 = kr[2 * s];
            k1 = kr[2 * s + 1];
            v0 = vr[2 * s];
            v1 = vr[2 * s + 1];
        }

        // partial dots for the (up to) 4 in-band queries at this t
        float d0 = 0.f, d1 = 0.f, d2 = 0.f, d3 = 0.f;
        if (t <= 2 * HW)               d0 = dot4(qv[0][0], k0) + dot4(qv[0][1], k1);
        if (t >= 1 && t <= 1 + 2 * HW) d1 = dot4(qv[1][0], k0) + dot4(qv[1][1], k1);
        if (t >= 2 && t <= 2 + 2 * HW) d2 = dot4(qv[2][0], k0) + dot4(qv[2][1], k1);
        if (t >= 3)                    d3 = dot4(qv[3][0], k0) + dot4(qv[3][1], k1);

        // Packed butterfly: 4 shfl; lane mos ends with query mos's full dot
        const bool odd = (s & 1);
        float a  = odd ? d0 : d2;
        float ta = __shfl_xor_sync(FULLM, a, 1);
        float bb = odd ? d1 : d3;
        float tb = __shfl_xor_sync(FULLM, bb, 1);
        float e0 = odd ? (d2 + ta) : (d0 + ta);
        float e1 = odd ? (d3 + tb) : (d1 + tb);
        const bool hi = (s & 2);
        float c  = hi ? e0 : e1;
        float tc = __shfl_xor_sync(FULLM, c, 2);
        float f  = hi ? (e1 + tc) : (e0 + tc);
        f += __shfl_xor_sync(FULLM, f, 4);

        // unnormalized weight (exp-on-the-fly; scores ~N(0,1), fp32-safe)
        const float e = valid ? __expf(f * SCALE) : 0.f;

        // owner-lane sum: lane's query mos is in band iff t in [mos, mos+8]
        if (t >= mos && t <= mos + 2 * HW) sum += e;

        // accumulate for each in-band query (band check compile-time)
#pragma unroll
        for (int mm = 0; mm < QPG; ++mm) {
            if (t >= mm && t <= mm + 2 * HW) {
                const int src = ((mm >> 1) & 1) | ((mm & 1) << 1);  // owner lane
                const float wm = __shfl_sync(FULLM, e, src, 8);
                fma4(acc[mm][0], wm, v0);
                fma4(acc[mm][1], wm, v1);
            }
        }
    }

    // ---- Normalize: broadcast 1/sum from each owner lane ----
    const float inv = 1.0f / sum;
#pragma unroll
    for (int mm = 0; mm < QPG; ++mm) {
        const int src = ((mm >> 1) & 1) | ((mm & 1) << 1);
        const float im = __shfl_sync(FULLM, inv, src, 8);
        acc[mm][0].x *= im; acc[mm][0].y *= im; acc[mm][0].z *= im; acc[mm][0].w *= im;
        acc[mm][1].x *= im; acc[mm][1].y *= im; acc[mm][1].z *= im; acc[mm][1].w *= im;
    }

    // ---- Store ----
#pragma unroll
    for (int m = 0; m < QPG; ++m) {
        float4* op = (float4*)(out + base + (size_t)(i0 + m) * DMODEL);
        op[2 * s]     = acc[m][0];
        op[2 * s + 1] = acc[m][1];
    }
}

extern "C" void kernel_launch(void* const* d_in, const int* in_sizes, int n_in,
                              void* d_out, int out_size)
{
    const float* q = (const float*)d_in[0];
    const float* k = (const float*)d_in[1];
    const float* v = (const float*)d_in[2];
    float* out = (float*)d_out;

    dim3 grid(SEQ / QT, NHEADS, 256);   // (2, 16, 256)
    dim3 block(128);                    // 16 groups x 4 queries
    banded_attn_kernel<<<grid, block>>>(q, k, v, out);
}

// round 16
// speedup vs baseline: 1.0085x; 1.0085x over previous
#include <cuda_runtime.h>
#include <cuda_pipeline_primitives.h>
#include <math_constants.h>

// Banded sparse attention, B=256, S=128, D=1024, H=16, Dh=64, |i-j|<=4.
// R6 two-pass core + ONE change: v band prefetched to smem via cp.async
// at CTA start; the k score pass covers the DMA latency; pass 2 reads v
// from smem (LDS.128, conflict-free, no validity branches).

#define SEQ    128
#define DMODEL 1024
#define NHEADS 16
#define HEADD  64
#define HW     4
#define BANDW  9
#define QPG    4              // queries per group
#define NT     (QPG + 2*HW)   // 12 band rows per group
#define QT     64             // queries per CTA
#define VROWS  (QT + 2*HW)    // 72 v rows staged
#define SCALE  0.125f
#define FULLM  0xffffffffu

__device__ __forceinline__ float dot4(const float4 a, const float4 b) {
    return a.x * b.x + a.y * b.y + a.z * b.z + a.w * b.w;
}
__device__ __forceinline__ void fma4(float4& a, float w, const float4 v) {
    a.x += w * v.x; a.y += w * v.y; a.z += w * v.z; a.w += w * v.w;
}

__global__ __launch_bounds__(128, 7)
void banded_attn_kernel(const float* __restrict__ q,
                        const float* __restrict__ k,
                        const float* __restrict__ v,
                        float* __restrict__ out)
{
    __shared__ float vsm[VROWS * HEADD];   // 18432 B

    const int b   = blockIdx.z;
    const int h   = blockIdx.y;
    const int q0  = blockIdx.x * QT;
    const int j0  = q0 - HW;               // first staged row (may be <0)
    const int tid = threadIdx.x;

    const int g   = tid >> 3;          // group 0..15
    const int s   = tid & 7;           // lane in group; owns float4 cols 2s,2s+1
    const int i0l = g * QPG;           // local first query of group
    const int i0  = q0 + i0l;
    const int j0g = i0 - HW;
    const int mos = ((s & 1) << 1) | ((s >> 1) & 1);   // owned query index

    const size_t base = ((size_t)b * SEQ) * DMODEL + (size_t)h * HEADD;

    // ---- Kick off v-band prefetch: 9 x 16B cp.async per thread ----
    {
        const float* vb = v + base;
#pragma unroll
        for (int idx = tid; idx < VROWS * (HEADD / 4); idx += 128) {
            const int r = idx >> 4;        // row 0..71
            const int c = idx & 15;        // float4 col
            const int j = j0 + r;
            float4* dst = (float4*)&vsm[r * HEADD + c * 4];
            if (j >= 0 && j < SEQ) {
                __pipeline_memcpy_async(dst,
                    (const float4*)(vb + (size_t)j * DMODEL) + c,
                    sizeof(float4));
            } else {
                *dst = make_float4(0.f, 0.f, 0.f, 0.f);
            }
        }
        __pipeline_commit();
    }

    // ---- q rows (8 dims per lane per query) ----
    float4 qv[QPG][2];
#pragma unroll
    for (int m = 0; m < QPG; ++m) {
        const float4* qp = (const float4*)(q + base + (size_t)(i0 + m) * DMODEL);
        qv[m][0] = qp[2 * s];
        qv[m][1] = qp[2 * s + 1];
    }

    // Per-lane weight vector for its owned query
    float w[BANDW];

    // ---- Scores over 12 shared k rows; packed 4-value butterfly reduce ----
    const float* kb = k + base;
#pragma unroll
    for (int t = 0; t < NT; ++t) {
        const int j = j0g + t;
        const bool valid = (j >= 0) && (j < SEQ);
        float4 k0 = make_float4(0.f, 0.f, 0.f, 0.f);
        float4 k1 = k0;
        if (valid) {
            const float4* kr = (const float4*)(kb + (size_t)j * DMODEL);
            k0 = kr[2 * s];
            k1 = kr[2 * s + 1];
        }

        float d0 = 0.f, d1 = 0.f, d2 = 0.f, d3 = 0.f;
        if (t >= 0 && t <= 0 + 2 * HW) d0 = dot4(qv[0][0], k0) + dot4(qv[0][1], k1);
        if (t >= 1 && t <= 1 + 2 * HW) d1 = dot4(qv[1][0], k0) + dot4(qv[1][1], k1);
        if (t >= 2 && t <= 2 + 2 * HW) d2 = dot4(qv[2][0], k0) + dot4(qv[2][1], k1);
        if (t >= 3 && t <= 3 + 2 * HW) d3 = dot4(qv[3][0], k0) + dot4(qv[3][1], k1);

        // Packed butterfly: 4 shfl; lane mos ends with query mos's dot
        const bool odd = (s & 1);
        float a  = odd ? d0 : d2;
        float ta = __shfl_xor_sync(FULLM, a, 1);
        float bb = odd ? d1 : d3;
        float tb = __shfl_xor_sync(FULLM, bb, 1);
        float e0 = odd ? (d2 + ta) : (d0 + ta);
        float e1 = odd ? (d3 + tb) : (d1 + tb);
        const bool hi = (s & 2);
        float c  = hi ? e0 : e1;
        float tc = __shfl_xor_sync(FULLM, c, 2);
        float f  = hi ? (e1 + tc) : (e0 + tc);
        f += __shfl_xor_sync(FULLM, f, 4);

        const float sc = valid ? f * SCALE : -CUDART_INF_F;
#pragma unroll
        for (int mm = 0; mm < QPG; ++mm) {
            if (t >= mm && t <= mm + 2 * HW) {      // compile-time
                if (mos == mm) w[t - mm] = sc;       // predicated select
            }
        }
    }

    // ---- Softmax: lane-local over the owned query's 9 weights ----
    {
        float mx = -CUDART_INF_F;
#pragma unroll
        for (int o = 0; o < BANDW; ++o) mx = fmaxf(mx, w[o]);
        float sum = 0.f;
#pragma unroll
        for (int o = 0; o < BANDW; ++o) { w[o] = __expf(w[o] - mx); sum += w[o]; }
        const float inv = 1.0f / sum;
#pragma unroll
        for (int o = 0; o < BANDW; ++o) w[o] *= inv;
    }

    // ---- Wait for v DMA, then weighted V from smem ----
    __pipeline_wait_prior(0);
    __syncthreads();

    float4 acc[QPG][2];
#pragma unroll
    for (int m = 0; m < QPG; ++m) {
        acc[m][0] = make_float4(0.f, 0.f, 0.f, 0.f);
        acc[m][1] = acc[m][0];
    }
#pragma unroll
    for (int t = 0; t < NT; ++t) {
        // smem row = (j - j0) = i0l + t; OOB rows hold zeros
        const float* vrow = &vsm[(i0l + t) * HEADD];
        const float4 v0 = *(const float4*)&vrow[8 * s];
        const float4 v1 = *(const float4*)&vrow[8 * s + 4];
#pragma unroll
        for (int mm = 0; mm < QPG; ++mm) {
            if (t >= mm && t <= mm + 2 * HW) {      // compile-time
                const int src = ((mm >> 1) & 1) | ((mm & 1) << 1);  // owner lane
                const float wm = __shfl_sync(FULLM, w[t - mm], src, 8);
                fma4(acc[mm][0], wm, v0);
                fma4(acc[mm][1], wm, v1);
            }
        }
    }

    // ---- Store ----
#pragma unroll
    for (int m = 0; m < QPG; ++m) {
        float4* op = (float4*)(out + base + (size_t)(i0 + m) * DMODEL);
        op[2 * s]     = acc[m][0];
        op[2 * s + 1] = acc[m][1];
    }
}

extern "C" void kernel_launch(void* const* d_in, const int* in_sizes, int n_in,
                              void* d_out, int out_size)
{
    const float* q = (const float*)d_in[0];
    const float* k = (const float*)d_in[1];
    const float* v = (const float*)d_in[2];
    float* out = (float*)d_out;

    dim3 grid(SEQ / QT, NHEADS, 256);   // (2, 16, 256)
    dim3 block(128);                    // 16 groups x 4 queries
    banded_attn_kernel<<<grid, block>>>(q, k, v, out);
}